// round 5
// baseline (speedup 1.0000x reference)
#include <cuda_runtime.h>
#include <math.h>

#define Bv 2
#define Nv 4096
#define Cv 64
#define TOPKv 24
#define MAXM 1024

// Output layout (concatenated, float32):
// expected (B,N,3) | disp (B,3,N) | probs (B,N,N) | conf (B,N) | ent (B,N) | src_pos (B,N,3)
#define EXP_OFF   ((size_t)0)
#define DISP_OFF  ((size_t)(Bv*Nv*3))
#define PROBS_OFF ((size_t)(2*Bv*Nv*3))
#define CONF_OFF  (PROBS_OFF + (size_t)Bv*Nv*Nv)
#define ENT_OFF   (CONF_OFF + (size_t)Bv*Nv)
#define SP_OFF    (ENT_OFF + (size_t)Bv*Nv)

// Scratch (no cudaMalloc allowed)
__device__ float g_tdT[(size_t)Bv*Nv*Cv];   // tgt_desc transposed: (B,N,64)
__device__ float g_tn2[Bv*Nv];              // ||tgt_canonical||^2 per node
__device__ float g_tlog[Bv*Nv];             // max(log softmax(tgt_mlogits)[...,0], -20)

__global__ void prep_kernel(const float* __restrict__ td,
                            const float* __restrict__ tc,
                            const float* __restrict__ tml) {
    int idx = blockIdx.x * blockDim.x + threadIdx.x;
    if (idx < Bv * Cv * Nv) {
        int b = idx / (Cv * Nv);
        int r = idx - b * (Cv * Nv);
        int c = r / Nv;
        int j = r - c * Nv;
        g_tdT[(((size_t)b * Nv + j) << 6) + c] = td[idx];
    }
    if (idx < Bv * Nv) {
        int b = idx >> 12, j = idx & (Nv - 1);
        const float* t = tc + (size_t)b * 3 * Nv;
        float x = t[j], y = t[Nv + j], z = t[2 * Nv + j];
        g_tn2[idx] = x * x + y * y + z * z;
        float l0 = tml[(size_t)b * 2 * Nv + j];
        float l1 = tml[(size_t)b * 2 * Nv + Nv + j];
        // log(softmax[...,0]) = -log1p(exp(l1-l0)); overflow -> -inf -> clamped to -20
        g_tlog[idx] = fmaxf(-log1pf(expf(l1 - l0)), -20.0f);
    }
}

__device__ __forceinline__ float bsumf(float v, float* buf) {
#pragma unroll
    for (int o = 16; o; o >>= 1) v += __shfl_xor_sync(0xffffffffu, v, o);
    if ((threadIdx.x & 31) == 0) buf[threadIdx.x >> 5] = v;
    __syncthreads();
    if (threadIdx.x == 0) {
        float s = buf[0];
#pragma unroll
        for (int w = 1; w < 8; w++) s += buf[w];
        buf[0] = s;
    }
    __syncthreads();
    float r = buf[0];
    __syncthreads();
    return r;
}

__device__ __forceinline__ float bmaxf(float v, float* buf) {
#pragma unroll
    for (int o = 16; o; o >>= 1) v = fmaxf(v, __shfl_xor_sync(0xffffffffu, v, o));
    if ((threadIdx.x & 31) == 0) buf[threadIdx.x >> 5] = v;
    __syncthreads();
    if (threadIdx.x == 0) {
        float s = buf[0];
#pragma unroll
        for (int w = 1; w < 8; w++) s = fmaxf(s, buf[w]);
        buf[0] = s;
    }
    __syncthreads();
    float r = buf[0];
    __syncthreads();
    return r;
}

__device__ __forceinline__ int bsumi(int v, int* buf) {
#pragma unroll
    for (int o = 16; o; o >>= 1) v += __shfl_xor_sync(0xffffffffu, v, o);
    if ((threadIdx.x & 31) == 0) buf[threadIdx.x >> 5] = v;
    __syncthreads();
    if (threadIdx.x == 0) {
        int s = buf[0];
#pragma unroll
        for (int w = 1; w < 8; w++) s += buf[w];
        buf[0] = s;
    }
    __syncthreads();
    int r = buf[0];
    __syncthreads();
    return r;
}

// Fused (min, tie-count) block reduction
__device__ __forceinline__ void bmincnt(float& m, int& c, float* bufm, int* bufc) {
#pragma unroll
    for (int o = 16; o; o >>= 1) {
        float om = __shfl_xor_sync(0xffffffffu, m, o);
        int oc = __shfl_xor_sync(0xffffffffu, c, o);
        if (om < m) { m = om; c = oc; }
        else if (om == m) c += oc;
    }
    if ((threadIdx.x & 31) == 0) { bufm[threadIdx.x >> 5] = m; bufc[threadIdx.x >> 5] = c; }
    __syncthreads();
    if (threadIdx.x == 0) {
        float mm = bufm[0]; int cc = bufc[0];
#pragma unroll
        for (int w = 1; w < 8; w++) {
            if (bufm[w] < mm) { mm = bufm[w]; cc = bufc[w]; }
            else if (bufm[w] == mm) cc += bufc[w];
        }
        bufm[0] = mm; bufc[0] = cc;
    }
    __syncthreads();
    m = bufm[0]; c = bufc[0];
    __syncthreads();
}

__global__ void __launch_bounds__(256)
matcher_kernel(const float* __restrict__ src_can,
               const float* __restrict__ tgt_can,
               const float* __restrict__ src_desc,
               const float* __restrict__ src_ml,
               const float* __restrict__ src_unc,
               const float* __restrict__ tgt_unc,
               float* __restrict__ out) {
    __shared__ float s_sd[64];
    __shared__ int   s_idx[MAXM];
    __shared__ float s_d2a[MAXM];
    __shared__ float s_val[MAXM];
    __shared__ float s_bm[8];
    __shared__ int   s_bc[8];
    __shared__ int   s_cnt;

    const int tid = threadIdx.x;
    const int bi = blockIdx.x;
    const int b = bi >> 12;
    const int i = bi & (Nv - 1);
    const int bN = b * Nv;

    // Zero this row of probs output (134MB total across grid; done once, coalesced)
    float4* rowz = reinterpret_cast<float4*>(out + PROBS_OFF + (size_t)(bN + i) * Nv);
#pragma unroll
    for (int k = 0; k < 4; k++) rowz[tid + 256 * k] = make_float4(0.f, 0.f, 0.f, 0.f);

    // Source descriptor into smem (64 floats)
    if (tid < 64) s_sd[tid] = src_desc[((size_t)b * 64 + tid) * Nv + i];
    if (tid == 0) s_cnt = 0;

    const float* sc = src_can + (size_t)b * 3 * Nv;
    float sx = sc[i], sy = sc[Nv + i], sz = sc[2 * Nv + i];
    float sn2 = sx * sx + sy * sy + sz * sz;

    const float* tc = tgt_can + (size_t)b * 3 * Nv;
    const float* tn2p = g_tn2 + bN;

    // All 4096 squared distances, 16 per thread in registers
    float d2v[16];
#pragma unroll
    for (int k = 0; k < 16; k++) {
        int j = (k << 8) + tid;
        float tx = tc[j], ty = tc[Nv + j], tz = tc[2 * Nv + j];
        float dot = sx * tx + sy * ty + sz * tz;
        d2v[k] = sn2 + tn2p[j] - 2.0f * dot;
    }
    __syncthreads();

    // allowed = (dist <= RADIUS) OR (j in top-24 smallest dist)
    //         = d2 <= max(24th-smallest d2, RADIUS^2)   (ties are measure-zero)
    const float R2 = 0.45f * 0.45f;
    int cloc = 0;
#pragma unroll
    for (int k = 0; k < 16; k++) cloc += (d2v[k] <= R2) ? 1 : 0;
    int ctot = bsumi(cloc, s_bc);

    float tau = R2;
    while (ctot < TOPKv) {
        float m = 3.4e38f; int c = 0;
#pragma unroll
        for (int k = 0; k < 16; k++) {
            float v = d2v[k];
            if (v > tau) {
                if (v < m) { m = v; c = 1; }
                else if (v == m) c++;
            }
        }
        bmincnt(m, c, s_bm, s_bc);
        if (m >= 3.4e38f) break;
        tau = m; ctot += c;
    }

    // Gather allowed indices
#pragma unroll
    for (int k = 0; k < 16; k++) {
        if (d2v[k] <= tau) {
            int p = atomicAdd(&s_cnt, 1);
            if (p < MAXM) { s_idx[p] = (k << 8) + tid; s_d2a[p] = d2v[k]; }
        }
    }
    __syncthreads();
    int M = min(s_cnt, MAXM);

    // Scores for allowed pairs only: warp-per-pair 64-dim descriptor dot
    const int warp = tid >> 5, lane = tid & 31;
    float sunc = src_unc[bN + i];
    for (int p = warp; p < M; p += 8) {
        int j = s_idx[p];
        const float* tdj = g_tdT + ((size_t)(bN + j) << 6);
        float part = tdj[lane] * s_sd[lane] + tdj[lane + 32] * s_sd[lane + 32];
#pragma unroll
        for (int o = 16; o; o >>= 1) part += __shfl_xor_sync(0xffffffffu, part, o);
        if (lane == 0) {
            float dist = sqrtf(fmaxf(s_d2a[p], 1e-12f));
            s_val[p] = part - dist - 0.1f * (sunc + tgt_unc[bN + j]) + g_tlog[bN + j];
        }
    }
    __syncthreads();

    // Softmax over the sparse allowed set (disallowed entries underflow to exact 0
    // in the reference as well: exp(-1e4/0.07) == 0 in fp32)
    float lm = -3.4e38f;
    for (int p = tid; p < M; p += 256) lm = fmaxf(lm, s_val[p]);
    float mx = bmaxf(lm, s_bm);

    const float invT = 1.0f / 0.07f;
    const float step = 2.0f / 15.0f;
    float Z = 0.f, eu = 0.f, e0 = 0.f, e1 = 0.f, e2 = 0.f, em = 0.f;
    for (int p = tid; p < M; p += 256) {
        float u = (s_val[p] - mx) * invT;
        float e = expf(u);
        s_val[p] = e;
        Z += e; eu += e * u; em = fmaxf(em, e);
        int j = s_idx[p];
        float c0 = (float)(j >> 8) * step - 1.0f;
        float c1 = (float)((j >> 4) & 15) * step - 1.0f;
        float c2 = (float)(j & 15) * step - 1.0f;
        e0 += e * c0; e1 += e * c1; e2 += e * c2;
    }
    Z  = bsumf(Z, s_bm);
    eu = bsumf(eu, s_bm);
    e0 = bsumf(e0, s_bm);
    e1 = bsumf(e1, s_bm);
    e2 = bsumf(e2, s_bm);
    em = bmaxf(em, s_bm);

    float invZ = 1.0f / Z;
    float* rowp = out + PROBS_OFF + (size_t)(bN + i) * Nv;
    for (int p = tid; p < M; p += 256) rowp[s_idx[p]] = s_val[p] * invZ;

    if (tid == 0) {
        float Ex0 = e0 * invZ, Ex1 = e1 * invZ, Ex2 = e2 * invZ;
        float p0 = (float)(i >> 8) * step - 1.0f;
        float p1 = (float)((i >> 4) & 15) * step - 1.0f;
        float p2 = (float)(i & 15) * step - 1.0f;
        size_t ri = (size_t)(bN + i);
        out[EXP_OFF + ri * 3 + 0] = Ex0;
        out[EXP_OFF + ri * 3 + 1] = Ex1;
        out[EXP_OFF + ri * 3 + 2] = Ex2;
        out[DISP_OFF + (size_t)b * 3 * Nv + 0 * Nv + i] = Ex0 - p0;
        out[DISP_OFF + (size_t)b * 3 * Nv + 1 * Nv + i] = Ex1 - p1;
        out[DISP_OFF + (size_t)b * 3 * Nv + 2 * Nv + i] = Ex2 - p2;
        float l0 = src_ml[(size_t)b * 2 * Nv + i];
        float l1 = src_ml[(size_t)b * 2 * Nv + Nv + i];
        float smatch = 1.0f / (1.0f + expf(l1 - l0));
        out[CONF_OFF + ri] = em * invZ * smatch;
        // ent = -sum p log p = logZ - (sum e*u)/Z   with u = (s - max)/T
        out[ENT_OFF + ri] = logf(Z) - eu * invZ;
        out[SP_OFF + ri * 3 + 0] = p0;
        out[SP_OFF + ri * 3 + 1] = p1;
        out[SP_OFF + ri * 3 + 2] = p2;
    }
}

extern "C" void kernel_launch(void* const* d_in, const int* in_sizes, int n_in,
                              void* d_out, int out_size) {
    const float* src_can  = (const float*)d_in[0];
    const float* tgt_can  = (const float*)d_in[1];
    const float* src_desc = (const float*)d_in[2];
    const float* tgt_desc = (const float*)d_in[3];
    const float* src_ml   = (const float*)d_in[4];
    const float* tgt_ml   = (const float*)d_in[5];
    const float* src_unc  = (const float*)d_in[6];
    const float* tgt_unc  = (const float*)d_in[7];
    float* out = (float*)d_out;

    prep_kernel<<<(Bv * Cv * Nv + 255) / 256, 256>>>(tgt_desc, tgt_can, tgt_ml);
    matcher_kernel<<<Bv * Nv, 256>>>(src_can, tgt_can, src_desc, src_ml,
                                     src_unc, tgt_unc, out);
}